// round 3
// baseline (speedup 1.0000x reference)
#include <cuda_runtime.h>
#include <cstdint>

#define SEQL 2048
#define EDIM 300
#define XPLD 1200

// ---- scratch (device globals; allocation is forbidden) ----
__device__ float g_E[SEQL * EDIM];
__device__ float g_XP[SEQL * XPLD];
__device__ float g_HS[SEQL * 300];
__device__ float g_OUTS[SEQL * 300];
__device__ float g_OUTE[SEQL * 300];
__device__ float g_ACC[1200];   // [0:600]=H_HAT(sent), [600:1200]=H_BAR(emo)

__device__ __forceinline__ uint32_t smem_u32(const void* p) {
    uint32_t a;
    asm("{ .reg .u64 t; cvta.to.shared.u64 t, %1; cvt.u32.u64 %0, t; }"
        : "=r"(a) : "l"(p));
    return a;
}

__device__ __forceinline__ float fast_sigmoid(float x) {
    return __fdividef(1.f, 1.f + __expf(-x));
}
__device__ __forceinline__ float fast_tanh(float x) {
    return __fdividef(2.f, 1.f + __expf(-2.f * x)) - 1.f;
}

// ---- kernel 1: embedding gather ----
__global__ void gather_kernel(const int* __restrict__ sent, const float* __restrict__ EM) {
    int i = blockIdx.x * 256 + threadIdx.x;
    if (i < SEQL * EDIM) {
        int s = i / EDIM, e = i - s * EDIM;
        g_E[i] = EM[(size_t)sent[s] * EDIM + e];
    }
}

// ---- kernel 2: generic GEMM + bias. 16-row tiles, K=300. ----
__global__ void __launch_bounds__(128) gemm_bias_kernel(
    const float* __restrict__ A, const float* __restrict__ B,
    const float* __restrict__ bias, float* __restrict__ C,
    int K, int N, int ldc, int cofs)
{
    __shared__ float As[16 * 300];
    int tid = threadIdx.x;
    int row0 = blockIdx.x * 16;
    for (int i = tid; i < 16 * K; i += 128) As[i] = A[(size_t)row0 * K + i];
    __syncthreads();
    int c = blockIdx.y * 128 + tid;
    if (c >= N) return;
    float acc[16];
    float bv = bias[c];
#pragma unroll
    for (int i = 0; i < 16; i++) acc[i] = bv;
    for (int k = 0; k < K; k++) {
        float w = B[(size_t)k * N + c];
#pragma unroll
        for (int i = 0; i < 16; i++) acc[i] = fmaf(As[i * K + k], w, acc[i]);
    }
#pragma unroll
    for (int i = 0; i < 16; i++) C[(size_t)(row0 + i) * ldc + cofs + c] = acc[i];
}

// ---- kernel 3: LSTM scan. grid=4, cluster(2): blocks {0,1}=fwd, {2,3}=bwd.
// Each CTA owns 300 z-columns of U (rank0: i,f; rank1: g,o), register-resident
// as 75 f32x2 per thread. Per step: 150-dot per thread, z-halves exchanged via
// st.shared::cluster + per-warp mbarrier arrives (double-buffered slots).
__global__ void __cluster_dims__(2, 1, 1) __launch_bounds__(320, 1)
lstm_kernel(const float* __restrict__ Uf, const float* __restrict__ Ub)
{
    __shared__ __align__(16) float h_s[152];
    __shared__ float z_own[304];
    __shared__ float z_in[2][304];
    __shared__ __align__(8) unsigned long long mbar[2];

    int tid = threadIdx.x;
    uint32_t rank;
    asm("mov.u32 %0, %%cluster_ctarank;" : "=r"(rank));
    int dir = blockIdx.x >> 1;

    if (tid < 152) h_s[tid] = 0.f;

    uint32_t mb[2];
    mb[0] = smem_u32(&mbar[0]);
    mb[1] = smem_u32(&mbar[1]);
    if (tid == 0) {
        // 10 local warp-arrives(32) + 10 remote warp-arrives(32) = 640 per phase
        asm volatile("mbarrier.init.shared.b64 [%0], %1;" :: "r"(mb[0]), "r"(640) : "memory");
        asm volatile("mbarrier.init.shared.b64 [%0], %1;" :: "r"(mb[1]), "r"(640) : "memory");
    }
    __syncthreads();

    uint32_t peer = rank ^ 1u;
    uint32_t rz[2], rmb[2];
    {
        uint32_t l0 = smem_u32(&z_in[0][0]);
        uint32_t l1 = smem_u32(&z_in[1][0]);
        asm("mapa.shared::cluster.u32 %0, %1, %2;" : "=r"(rz[0]) : "r"(l0), "r"(peer));
        asm("mapa.shared::cluster.u32 %0, %1, %2;" : "=r"(rz[1]) : "r"(l1), "r"(peer));
        asm("mapa.shared::cluster.u32 %0, %1, %2;" : "=r"(rmb[0]) : "r"(mb[0]), "r"(peer));
        asm("mapa.shared::cluster.u32 %0, %1, %2;" : "=r"(rmb[1]) : "r"(mb[1]), "r"(peer));
    }

    const float* U = dir ? Ub : Uf;
    int c = (int)rank * 300 + tid;

    unsigned long long u[75];
    if (tid < 300) {
#pragma unroll
        for (int kk = 0; kk < 75; kk++) {
            float lo = U[(2 * kk) * 600 + c];
            float hi = U[(2 * kk + 1) * 600 + c];
            asm("mov.b64 %0, {%1, %2};" : "=l"(u[kk]) : "f"(lo), "f"(hi));
        }
    }

    const float* xp = g_XP + (size_t)dir * 600 + (size_t)rank * 300 + tid;
    float c_val = 0.f;

    // both CTAs' mbarriers must be initialized before any remote arrive
    asm volatile("barrier.cluster.arrive.aligned;" ::: "memory");
    asm volatile("barrier.cluster.wait.aligned;" ::: "memory");

    for (int ti = 0; ti < SEQL; ti++) {
        int t = dir ? (SEQL - 1 - ti) : ti;
        int slot = ti & 1;
        uint32_t parity = (uint32_t)((ti >> 1) & 1);

        if (tid < 300) {
            float xpv = __ldg(xp + (size_t)t * XPLD);
            unsigned long long a0 = 0ull, a1 = 0ull, a2 = 0ull, a3 = 0ull;
            const unsigned long long* hp = reinterpret_cast<const unsigned long long*>(h_s);
#pragma unroll
            for (int kk = 0; kk < 75; kk += 4) {
                asm("fma.rn.f32x2 %0, %1, %2, %0;" : "+l"(a0) : "l"(hp[kk]),     "l"(u[kk]));
                asm("fma.rn.f32x2 %0, %1, %2, %0;" : "+l"(a1) : "l"(hp[kk + 1]), "l"(u[kk + 1]));
                asm("fma.rn.f32x2 %0, %1, %2, %0;" : "+l"(a2) : "l"(hp[kk + 2]), "l"(u[kk + 2]));
                if (kk + 3 < 75)
                    asm("fma.rn.f32x2 %0, %1, %2, %0;" : "+l"(a3) : "l"(hp[kk + 3]), "l"(u[kk + 3]));
            }
            asm("add.rn.f32x2 %0, %0, %1;" : "+l"(a0) : "l"(a1));
            asm("add.rn.f32x2 %0, %0, %1;" : "+l"(a2) : "l"(a3));
            asm("add.rn.f32x2 %0, %0, %1;" : "+l"(a0) : "l"(a2));
            float lo, hi;
            asm("mov.b64 {%0, %1}, %2;" : "=f"(lo), "=f"(hi) : "l"(a0));
            float z = lo + hi + xpv;
            z_own[tid] = z;
            asm volatile("st.shared::cluster.f32 [%0], %1;"
                         :: "r"(rz[slot] + (uint32_t)tid * 4u), "f"(z) : "memory");
        }
        __syncwarp();
        if ((tid & 31) == 0) {
            // local arrive: releases this warp's z_own stores to local waiters
            asm volatile("mbarrier.arrive.release.cluster.shared::cta.b64 _, [%0], %1;"
                         :: "r"(mb[slot]), "r"(32) : "memory");
            // remote arrive: release-cumulative over this warp's DSMEM z stores
            asm volatile("mbarrier.arrive.release.cluster.shared::cluster.b64 _, [%0], %1;"
                         :: "r"(rmb[slot]), "r"(32) : "memory");
        }
        {
            uint32_t done = 0;
            while (!done) {
                asm volatile(
                    "{ .reg .pred p;\n\t"
                    "mbarrier.try_wait.parity.acquire.cluster.shared::cta.b64 p, [%1], %2, 0x989680;\n\t"
                    "selp.b32 %0, 1, 0, p; }"
                    : "=r"(done) : "r"(mb[slot]), "r"(parity) : "memory");
            }
        }
        if (tid < 150) {
            const float* zin = z_in[slot];
            float zi, zf, zg, zo;
            if (rank == 0) { zi = z_own[tid]; zf = z_own[150 + tid]; zg = zin[tid]; zo = zin[150 + tid]; }
            else           { zg = z_own[tid]; zo = z_own[150 + tid]; zi = zin[tid]; zf = zin[150 + tid]; }
            float ig = fast_sigmoid(zi);
            float fg = fast_sigmoid(zf);
            float gg = fast_tanh(zg);
            float og = fast_sigmoid(zo);
            c_val = fg * c_val + ig * gg;
            float h = og * fast_tanh(c_val);
            h_s[tid] = h;
            if (rank == 0) g_HS[(size_t)t * 300 + dir * 150 + tid] = h;
        }
        __syncthreads();   // h_s visible to all warps before next dot
    }
    asm volatile("barrier.cluster.arrive.aligned;" ::: "memory");
    asm volatile("barrier.cluster.wait.aligned;" ::: "memory");
}

// ---- kernel 4: zero accumulators (must run every launch) ----
__global__ void zero_acc_kernel() {
    int i = blockIdx.x * 600 + threadIdx.x;
    if (i < 1200) g_ACC[i] = 0.f;
}

// ---- kernel 5: primary + secondary attention, one block per position ----
// fused 8-way block reduction (2 syncthreads instead of 24)
__global__ void __launch_bounds__(320) attention_kernel(
    const int* __restrict__ sent, const float* __restrict__ EM,
    const int* __restrict__ synidx,
    const float* __restrict__ w_se, const float* __restrict__ b_se,
    const float* __restrict__ w_ss, const float* __restrict__ b_ss)
{
    __shared__ float r[4][300];
    __shared__ int sidx[4];
    __shared__ float red[10][8];
    __shared__ float bcast[8];
    int tid = threadIdx.x;
    int lane = tid & 31, warp = tid >> 5;
    int s = blockIdx.x;
    if (tid < 4) sidx[tid] = synidx[(size_t)sent[s] * 4 + tid];
    __syncthreads();
    for (int i = tid; i < 4 * 300; i += 320) {
        int k = i / 300, d = i - k * 300;
        r[k][d] = EM[(size_t)sidx[k] * 300 + d];
    }
    __syncthreads();

    float os = 0.f, oe = 0.f, hsv = 0.f, r0 = 0.f, r1 = 0.f, r2 = 0.f, r3 = 0.f;
    if (tid < 300) {
        os = g_OUTS[s * 300 + tid];
        oe = g_OUTE[s * 300 + tid];
        hsv = g_HS[s * 300 + tid];
        r0 = r[0][tid]; r1 = r[1][tid]; r2 = r[2][tid]; r3 = r[3][tid];
    }
    float v[8] = { os * r0, os * r1, os * r2, os * r3,
                   oe * r0, oe * r1, oe * r2, oe * r3 };
#pragma unroll
    for (int k = 0; k < 8; k++)
#pragma unroll
        for (int o = 16; o; o >>= 1) v[k] += __shfl_down_sync(0xffffffffu, v[k], o);
    if (lane == 0)
#pragma unroll
        for (int k = 0; k < 8; k++) red[warp][k] = v[k];
    __syncthreads();
    if (tid < 8) {
        float sum = 0.f;
#pragma unroll
        for (int w = 0; w < 10; w++) sum += red[w][tid];
        bcast[tid] = expf(sum);
    }
    __syncthreads();

    float as0 = bcast[0], as1 = bcast[1], as2 = bcast[2], as3 = bcast[3];
    float ae0 = bcast[4], ae1 = bcast[5], ae2 = bcast[6], ae3 = bcast[7];
    float ms = as0 * r0 + as1 * r1 + as2 * r2 + as3 * r3;
    float me = ae0 * r0 + ae1 * r1 + ae2 * r2 + ae3 * r3;

    float ps = 0.f, pe = 0.f;
    if (tid < 300) {
        ps = hsv * w_ss[tid] + ms * w_ss[300 + tid];
        pe = hsv * w_se[tid] + me * w_se[300 + tid];
    }
    float v2[2] = { ps, pe };
#pragma unroll
    for (int k = 0; k < 2; k++)
#pragma unroll
        for (int o = 16; o; o >>= 1) v2[k] += __shfl_down_sync(0xffffffffu, v2[k], o);
    if (lane == 0) { red[warp][0] = v2[0]; red[warp][1] = v2[1]; }
    __syncthreads();
    if (tid < 2) {
        float sum = 0.f;
#pragma unroll
        for (int w = 0; w < 10; w++) sum += red[w][tid];
        float b = (tid == 0) ? b_ss[0] : b_se[0];
        bcast[tid] = expf(tanhf(sum + b));
    }
    __syncthreads();
    float coeff_s = bcast[0];
    float coeff_e = bcast[1];

    if (tid < 300) {
        atomicAdd(&g_ACC[tid],       coeff_s * hsv);
        atomicAdd(&g_ACC[300 + tid], coeff_s * ms);
        atomicAdd(&g_ACC[600 + tid], coeff_e * hsv);
        atomicAdd(&g_ACC[900 + tid], coeff_e * me);
    }
}

// ---- kernel 6: final logits. out[0..7]=emotion, out[8]=sentiment ----
__global__ void __launch_bounds__(288) final_kernel(
    const float* __restrict__ W_eo, const float* __restrict__ b_eo,
    const float* __restrict__ W_so, const float* __restrict__ b_so,
    float* __restrict__ out)
{
    int w = threadIdx.x >> 5, lane = threadIdx.x & 31;
    float p = 0.f;
    if (w < 8) {
        for (int d = lane; d < 600; d += 32) p += g_ACC[600 + d] * W_eo[d * 8 + w];
    } else {
        for (int d = lane; d < 600; d += 32) p += g_ACC[d] * W_so[d];
    }
#pragma unroll
    for (int o = 16; o; o >>= 1) p += __shfl_down_sync(0xffffffffu, p, o);
    if (lane == 0) out[w] = p + (w < 8 ? b_eo[w] : b_so[0]);
}

extern "C" void kernel_launch(void* const* d_in, const int* in_sizes, int n_in,
                              void* d_out, int out_size)
{
    (void)in_sizes; (void)n_in; (void)out_size;
    const int*   sent = (const int*)  d_in[0];
    const float* EM   = (const float*)d_in[1];
    const int*   syn  = (const int*)  d_in[2];
    const float* Wf   = (const float*)d_in[3];
    const float* Uf   = (const float*)d_in[4];
    const float* bf   = (const float*)d_in[5];
    const float* Wb   = (const float*)d_in[6];
    const float* Ub   = (const float*)d_in[7];
    const float* bb   = (const float*)d_in[8];
    const float* W_pe = (const float*)d_in[9];
    const float* b_pe = (const float*)d_in[10];
    const float* W_ps = (const float*)d_in[11];
    const float* b_ps = (const float*)d_in[12];
    const float* w_se = (const float*)d_in[13];
    const float* b_se = (const float*)d_in[14];
    const float* w_ss = (const float*)d_in[15];
    const float* b_ss = (const float*)d_in[16];
    const float* W_eo = (const float*)d_in[17];
    const float* b_eo = (const float*)d_in[18];
    const float* W_so = (const float*)d_in[19];
    const float* b_so = (const float*)d_in[20];
    float* out = (float*)d_out;

    float *pE, *pXP, *pHS, *pOS, *pOE;
    cudaGetSymbolAddress((void**)&pE,  g_E);
    cudaGetSymbolAddress((void**)&pXP, g_XP);
    cudaGetSymbolAddress((void**)&pHS, g_HS);
    cudaGetSymbolAddress((void**)&pOS, g_OUTS);
    cudaGetSymbolAddress((void**)&pOE, g_OUTE);

    gather_kernel<<<(SEQL * EDIM + 255) / 256, 256>>>(sent, EM);

    dim3 gxp(SEQL / 16, 5);   // N=600
    gemm_bias_kernel<<<gxp, 128>>>(pE, Wf, bf, pXP, 300, 600, XPLD, 0);
    gemm_bias_kernel<<<gxp, 128>>>(pE, Wb, bb, pXP, 300, 600, XPLD, 600);

    lstm_kernel<<<4, 320>>>(Uf, Ub);

    dim3 gout(SEQL / 16, 3);  // N=300
    gemm_bias_kernel<<<gout, 128>>>(pHS, W_ps, b_ps, pOS, 300, 300, 300, 0);
    gemm_bias_kernel<<<gout, 128>>>(pHS, W_pe, b_pe, pOE, 300, 300, 300, 0);

    zero_acc_kernel<<<2, 600>>>();
    attention_kernel<<<SEQL, 320>>>(sent, EM, syn, w_se, b_se, w_ss, b_ss);
    final_kernel<<<1, 288>>>(W_eo, b_eo, W_so, b_so, out);
}

// round 4
// speedup vs baseline: 1.0623x; 1.0623x over previous
#include <cuda_runtime.h>
#include <cstdint>

#define SEQL 2048
#define EDIM 300
#define XPLD 1200

// ---- scratch (device globals; allocation is forbidden) ----
__device__ float g_E[SEQL * EDIM];
__device__ float g_XP[SEQL * XPLD];
__device__ float g_HS[SEQL * 300];
__device__ float g_OUTS[SEQL * 300];
__device__ float g_OUTE[SEQL * 300];
__device__ float g_ACC[1200];   // [0:600]=H_HAT(sent), [600:1200]=H_BAR(emo)

__device__ __forceinline__ uint32_t smem_u32(const void* p) {
    uint32_t a;
    asm("{ .reg .u64 t; cvta.to.shared.u64 t, %1; cvt.u32.u64 %0, t; }"
        : "=r"(a) : "l"(p));
    return a;
}

__device__ __forceinline__ float fast_sigmoid(float x) {
    return __fdividef(1.f, 1.f + __expf(-x));
}
__device__ __forceinline__ float fast_tanh(float x) {
    return __fdividef(2.f, 1.f + __expf(-2.f * x)) - 1.f;
}

// ---- kernel 1: embedding gather ----
__global__ void gather_kernel(const int* __restrict__ sent, const float* __restrict__ EM) {
    int i = blockIdx.x * 256 + threadIdx.x;
    if (i < SEQL * EDIM) {
        int s = i / EDIM, e = i - s * EDIM;
        g_E[i] = EM[(size_t)sent[s] * EDIM + e];
    }
}

// ---- kernel 2: generic GEMM + bias. 16-row tiles, K=300. ----
__global__ void __launch_bounds__(128) gemm_bias_kernel(
    const float* __restrict__ A, const float* __restrict__ B,
    const float* __restrict__ bias, float* __restrict__ C,
    int K, int N, int ldc, int cofs)
{
    __shared__ float As[16 * 300];
    int tid = threadIdx.x;
    int row0 = blockIdx.x * 16;
    for (int i = tid; i < 16 * K; i += 128) As[i] = A[(size_t)row0 * K + i];
    __syncthreads();
    int c = blockIdx.y * 128 + tid;
    if (c >= N) return;
    float acc[16];
    float bv = bias[c];
#pragma unroll
    for (int i = 0; i < 16; i++) acc[i] = bv;
    for (int k = 0; k < K; k++) {
        float w = B[(size_t)k * N + c];
#pragma unroll
        for (int i = 0; i < 16; i++) acc[i] = fmaf(As[i * K + k], w, acc[i]);
    }
#pragma unroll
    for (int i = 0; i < 16; i++) C[(size_t)(row0 + i) * ldc + cofs + c] = acc[i];
}

// ---- kernel 3: LSTM scan. grid=4, cluster(2): blocks {0,1}=fwd, {2,3}=bwd.
// Gate-local layout: CTA rank owns ALL FOUR gates of hidden units
// [rank*75, rank*75+75). Thread t<300 owns global z-column
//   (t/75)*150 + rank*75 + (t%75).
// h stored padded: unit m -> slot (m<75 ? m : 76+(m-75)); slots 75,151 = 0 pad.
// Per step: dot over own h half (available locally), wait peer h (75 floats,
// DSMEM + per-thread release arrives), dot over peer half, gates local.
__global__ void __cluster_dims__(2, 1, 1) __launch_bounds__(320, 1)
lstm_kernel(const float* __restrict__ Uf, const float* __restrict__ Ub)
{
    __shared__ __align__(16) float h_s[2][152];
    __shared__ float z_own[304];
    __shared__ __align__(8) unsigned long long hb[2];

    int tid = threadIdx.x;
    uint32_t rank;
    asm("mov.u32 %0, %%cluster_ctarank;" : "=r"(rank));
    int dir = blockIdx.x >> 1;

    if (tid < 152) { h_s[0][tid] = 0.f; h_s[1][tid] = 0.f; }

    uint32_t mb[2];
    mb[0] = smem_u32(&hb[0]);
    mb[1] = smem_u32(&hb[1]);
    if (tid == 0) {
        asm volatile("mbarrier.init.shared.b64 [%0], %1;" :: "r"(mb[0]), "r"(75) : "memory");
        asm volatile("mbarrier.init.shared.b64 [%0], %1;" :: "r"(mb[1]), "r"(75) : "memory");
    }
    __syncthreads();

    uint32_t peer = rank ^ 1u;
    uint32_t h_base = smem_u32(&h_s[0][0]);
    uint32_t rh_base, rmb[2];
    {
        asm("mapa.shared::cluster.u32 %0, %1, %2;" : "=r"(rh_base) : "r"(h_base), "r"(peer));
        asm("mapa.shared::cluster.u32 %0, %1, %2;" : "=r"(rmb[0]) : "r"(mb[0]), "r"(peer));
        asm("mapa.shared::cluster.u32 %0, %1, %2;" : "=r"(rmb[1]) : "r"(mb[1]), "r"(peer));
    }

    const float* U = dir ? Ub : Uf;
    int gcol = (tid / 75) * 150 + (int)rank * 75 + (tid % 75); // global z column

    // U column register-resident, split own/peer h windows, zero-padded at
    // window slot 75 (the pad slot in each 76-wide half).
    unsigned long long u_own[38], u_pe[38];
    if (tid < 300) {
        int base_own = (int)rank * 75;
        int base_pe  = (int)peer * 75;
#pragma unroll
        for (int kk = 0; kk < 38; kk++) {
            int s0 = 2 * kk, s1 = 2 * kk + 1;
            float lo = (s0 < 75) ? U[(base_own + s0) * 600 + gcol] : 0.f;
            float hi = (s1 < 75) ? U[(base_own + s1) * 600 + gcol] : 0.f;
            asm("mov.b64 %0, {%1, %2};" : "=l"(u_own[kk]) : "f"(lo), "f"(hi));
            lo = (s0 < 75) ? U[(base_pe + s0) * 600 + gcol] : 0.f;
            hi = (s1 < 75) ? U[(base_pe + s1) * 600 + gcol] : 0.f;
            asm("mov.b64 %0, {%1, %2};" : "=l"(u_pe[kk]) : "f"(lo), "f"(hi));
        }
    }

    const float* xp = g_XP + (size_t)(dir ? (SEQL - 1) : 0) * XPLD + dir * 600 + gcol;
    const int xp_step = dir ? -XPLD : XPLD;
    float* hs_out = g_HS + (size_t)(dir ? (SEQL - 1) : 0) * 300 + dir * 150 + (int)rank * 75 + tid;
    const int hs_step = dir ? -300 : 300;

    float c_val = 0.f;

    // both CTAs' mbarriers must be initialized before any remote arrive
    asm volatile("barrier.cluster.arrive.aligned;" ::: "memory");
    asm volatile("barrier.cluster.wait.aligned;" ::: "memory");

    for (int ti = 0; ti < SEQL; ti++) {
        int b = ti & 1;
        uint32_t hbuf = h_base + (uint32_t)b * 608u;   // 152*4 bytes per buffer
        unsigned long long a0 = 0ull, a1 = 0ull, a2 = 0ull, a3 = 0ull;
        float xpv = 0.f;

        if (tid < 300) {
            xpv = __ldg(xp);
            uint32_t ao = hbuf + rank * 304u;          // own 76-slot window
#pragma unroll
            for (int q = 0; q < 19; q++) {
                unsigned long long p0, p1;
                asm("ld.shared.v2.u64 {%0, %1}, [%2];"
                    : "=l"(p0), "=l"(p1) : "r"(ao + (uint32_t)q * 16u));
                asm("fma.rn.f32x2 %0, %1, %2, %0;" : "+l"(a0) : "l"(p0), "l"(u_own[2 * q]));
                asm("fma.rn.f32x2 %0, %1, %2, %0;" : "+l"(a1) : "l"(p1), "l"(u_own[2 * q + 1]));
            }
        }
        if (ti > 0) {   // wait for peer's h half (sent at end of step ti-1)
            uint32_t parity = (uint32_t)(((ti - 1) >> 1) & 1);
            uint32_t done = 0;
            while (!done) {
                asm volatile(
                    "{ .reg .pred p;\n\t"
                    "mbarrier.try_wait.parity.acquire.cluster.shared::cta.b64 p, [%1], %2, 0x989680;\n\t"
                    "selp.b32 %0, 1, 0, p; }"
                    : "=r"(done) : "r"(mb[b]), "r"(parity) : "memory");
            }
        }
        if (tid < 300) {
            uint32_t ap = hbuf + peer * 304u;          // peer 76-slot window
#pragma unroll
            for (int q = 0; q < 19; q++) {
                unsigned long long p0, p1;
                asm("ld.shared.v2.u64 {%0, %1}, [%2];"
                    : "=l"(p0), "=l"(p1) : "r"(ap + (uint32_t)q * 16u));
                asm("fma.rn.f32x2 %0, %1, %2, %0;" : "+l"(a2) : "l"(p0), "l"(u_pe[2 * q]));
                asm("fma.rn.f32x2 %0, %1, %2, %0;" : "+l"(a3) : "l"(p1), "l"(u_pe[2 * q + 1]));
            }
            asm("add.rn.f32x2 %0, %0, %1;" : "+l"(a0) : "l"(a1));
            asm("add.rn.f32x2 %0, %0, %1;" : "+l"(a2) : "l"(a3));
            asm("add.rn.f32x2 %0, %0, %1;" : "+l"(a0) : "l"(a2));
            float lo, hi;
            asm("mov.b64 {%0, %1}, %2;" : "=f"(lo), "=f"(hi) : "l"(a0));
            z_own[tid] = lo + hi + xpv;
            xp += xp_step;
        }
        __syncthreads();   // z visible to gate threads

        if (tid < 75) {
            float zi = z_own[tid];
            float zf = z_own[75 + tid];
            float zg = z_own[150 + tid];
            float zo = z_own[225 + tid];
            float ig = fast_sigmoid(zi);
            float fg = fast_sigmoid(zf);
            float gg = fast_tanh(zg);
            float og = fast_sigmoid(zo);
            c_val = fg * c_val + ig * gg;
            float h = og * fast_tanh(c_val);
            int slot = (int)rank * 76 + tid;
            int bn = b ^ 1;
            h_s[bn][slot] = h;                         // local copy for next own-dot
            uint32_t raddr = rh_base + (uint32_t)bn * 608u + (uint32_t)slot * 4u;
            asm volatile("st.shared::cluster.f32 [%0], %1;" :: "r"(raddr), "f"(h) : "memory");
            // per-thread release arrive: orders THIS thread's DSMEM store
            asm volatile("mbarrier.arrive.release.cluster.shared::cluster.b64 _, [%0];"
                         :: "r"(rmb[bn]) : "memory");
            hs_out[0] = h;
        }
        if (tid < 75) hs_out += hs_step;
        __syncthreads();   // local h_s[bn] writes visible before next own-dot
    }
    asm volatile("barrier.cluster.arrive.aligned;" ::: "memory");
    asm volatile("barrier.cluster.wait.aligned;" ::: "memory");
}

// ---- kernel 4: zero accumulators (must run every launch) ----
__global__ void zero_acc_kernel() {
    int i = blockIdx.x * 600 + threadIdx.x;
    if (i < 1200) g_ACC[i] = 0.f;
}

// ---- kernel 5: primary + secondary attention, one block per position ----
__global__ void __launch_bounds__(320) attention_kernel(
    const int* __restrict__ sent, const float* __restrict__ EM,
    const int* __restrict__ synidx,
    const float* __restrict__ w_se, const float* __restrict__ b_se,
    const float* __restrict__ w_ss, const float* __restrict__ b_ss)
{
    __shared__ float r[4][300];
    __shared__ int sidx[4];
    __shared__ float red[10][8];
    __shared__ float bcast[8];
    int tid = threadIdx.x;
    int lane = tid & 31, warp = tid >> 5;
    int s = blockIdx.x;
    if (tid < 4) sidx[tid] = synidx[(size_t)sent[s] * 4 + tid];
    __syncthreads();
    for (int i = tid; i < 4 * 300; i += 320) {
        int k = i / 300, d = i - k * 300;
        r[k][d] = EM[(size_t)sidx[k] * 300 + d];
    }
    __syncthreads();

    float os = 0.f, oe = 0.f, hsv = 0.f, r0 = 0.f, r1 = 0.f, r2 = 0.f, r3 = 0.f;
    if (tid < 300) {
        os = g_OUTS[s * 300 + tid];
        oe = g_OUTE[s * 300 + tid];
        hsv = g_HS[s * 300 + tid];
        r0 = r[0][tid]; r1 = r[1][tid]; r2 = r[2][tid]; r3 = r[3][tid];
    }
    float v[8] = { os * r0, os * r1, os * r2, os * r3,
                   oe * r0, oe * r1, oe * r2, oe * r3 };
#pragma unroll
    for (int k = 0; k < 8; k++)
#pragma unroll
        for (int o = 16; o; o >>= 1) v[k] += __shfl_down_sync(0xffffffffu, v[k], o);
    if (lane == 0)
#pragma unroll
        for (int k = 0; k < 8; k++) red[warp][k] = v[k];
    __syncthreads();
    if (tid < 8) {
        float sum = 0.f;
#pragma unroll
        for (int w = 0; w < 10; w++) sum += red[w][tid];
        bcast[tid] = expf(sum);
    }
    __syncthreads();

    float as0 = bcast[0], as1 = bcast[1], as2 = bcast[2], as3 = bcast[3];
    float ae0 = bcast[4], ae1 = bcast[5], ae2 = bcast[6], ae3 = bcast[7];
    float ms = as0 * r0 + as1 * r1 + as2 * r2 + as3 * r3;
    float me = ae0 * r0 + ae1 * r1 + ae2 * r2 + ae3 * r3;

    float ps = 0.f, pe = 0.f;
    if (tid < 300) {
        ps = hsv * w_ss[tid] + ms * w_ss[300 + tid];
        pe = hsv * w_se[tid] + me * w_se[300 + tid];
    }
    float v2[2] = { ps, pe };
#pragma unroll
    for (int k = 0; k < 2; k++)
#pragma unroll
        for (int o = 16; o; o >>= 1) v2[k] += __shfl_down_sync(0xffffffffu, v2[k], o);
    if (lane == 0) { red[warp][0] = v2[0]; red[warp][1] = v2[1]; }
    __syncthreads();
    if (tid < 2) {
        float sum = 0.f;
#pragma unroll
        for (int w = 0; w < 10; w++) sum += red[w][tid];
        float b = (tid == 0) ? b_ss[0] : b_se[0];
        bcast[tid] = expf(tanhf(sum + b));
    }
    __syncthreads();
    float coeff_s = bcast[0];
    float coeff_e = bcast[1];

    if (tid < 300) {
        atomicAdd(&g_ACC[tid],       coeff_s * hsv);
        atomicAdd(&g_ACC[300 + tid], coeff_s * ms);
        atomicAdd(&g_ACC[600 + tid], coeff_e * hsv);
        atomicAdd(&g_ACC[900 + tid], coeff_e * me);
    }
}

// ---- kernel 6: final logits. out[0..7]=emotion, out[8]=sentiment ----
__global__ void __launch_bounds__(288) final_kernel(
    const float* __restrict__ W_eo, const float* __restrict__ b_eo,
    const float* __restrict__ W_so, const float* __restrict__ b_so,
    float* __restrict__ out)
{
    int w = threadIdx.x >> 5, lane = threadIdx.x & 31;
    float p = 0.f;
    if (w < 8) {
        for (int d = lane; d < 600; d += 32) p += g_ACC[600 + d] * W_eo[d * 8 + w];
    } else {
        for (int d = lane; d < 600; d += 32) p += g_ACC[d] * W_so[d];
    }
#pragma unroll
    for (int o = 16; o; o >>= 1) p += __shfl_down_sync(0xffffffffu, p, o);
    if (lane == 0) out[w] = p + (w < 8 ? b_eo[w] : b_so[0]);
}

extern "C" void kernel_launch(void* const* d_in, const int* in_sizes, int n_in,
                              void* d_out, int out_size)
{
    (void)in_sizes; (void)n_in; (void)out_size;
    const int*   sent = (const int*)  d_in[0];
    const float* EM   = (const float*)d_in[1];
    const int*   syn  = (const int*)  d_in[2];
    const float* Wf   = (const float*)d_in[3];
    const float* Uf   = (const float*)d_in[4];
    const float* bf   = (const float*)d_in[5];
    const float* Wb   = (const float*)d_in[6];
    const float* Ub   = (const float*)d_in[7];
    const float* bb   = (const float*)d_in[8];
    const float* W_pe = (const float*)d_in[9];
    const float* b_pe = (const float*)d_in[10];
    const float* W_ps = (const float*)d_in[11];
    const float* b_ps = (const float*)d_in[12];
    const float* w_se = (const float*)d_in[13];
    const float* b_se = (const float*)d_in[14];
    const float* w_ss = (const float*)d_in[15];
    const float* b_ss = (const float*)d_in[16];
    const float* W_eo = (const float*)d_in[17];
    const float* b_eo = (const float*)d_in[18];
    const float* W_so = (const float*)d_in[19];
    const float* b_so = (const float*)d_in[20];
    float* out = (float*)d_out;

    float *pE, *pXP, *pHS, *pOS, *pOE;
    cudaGetSymbolAddress((void**)&pE,  g_E);
    cudaGetSymbolAddress((void**)&pXP, g_XP);
    cudaGetSymbolAddress((void**)&pHS, g_HS);
    cudaGetSymbolAddress((void**)&pOS, g_OUTS);
    cudaGetSymbolAddress((void**)&pOE, g_OUTE);

    gather_kernel<<<(SEQL * EDIM + 255) / 256, 256>>>(sent, EM);

    dim3 gxp(SEQL / 16, 5);   // N=600
    gemm_bias_kernel<<<gxp, 128>>>(pE, Wf, bf, pXP, 300, 600, XPLD, 0);
    gemm_bias_kernel<<<gxp, 128>>>(pE, Wb, bb, pXP, 300, 600, XPLD, 600);

    lstm_kernel<<<4, 320>>>(Uf, Ub);

    dim3 gout(SEQL / 16, 3);  // N=300
    gemm_bias_kernel<<<gout, 128>>>(pHS, W_ps, b_ps, pOS, 300, 300, 300, 0);
    gemm_bias_kernel<<<gout, 128>>>(pHS, W_pe, b_pe, pOE, 300, 300, 300, 0);

    zero_acc_kernel<<<2, 600>>>();
    attention_kernel<<<SEQL, 320>>>(sent, EM, syn, w_se, b_se, w_ss, b_ss);
    final_kernel<<<1, 288>>>(W_eo, b_eo, W_so, b_so, out);
}